// round 2
// baseline (speedup 1.0000x reference)
#include <cuda_runtime.h>
#include <math.h>

// Problem constants
#define BB 2
#define TT 2048
#define HH 16
#define DD 64
#define CC 1024

// Scratch (device globals: allocation-free per harness rules)
__device__ float g_qkv[BB * TT * 3 * CC];         // 48 MB
__device__ float g_q[BB * HH * TT * DD];          // 16 MB
__device__ float g_k[BB * HH * TT * DD];          // 16 MB
__device__ float g_v[BB * HH * TT * DD];          // 16 MB
__device__ float g_y[BB * TT * CC];               // 16 MB

// ---------------------------------------------------------------------------
// SGEMM: C[m][n] = sum_k A[m][k] * B[n][k]   (both K-major, i.e. C = A * B^T)
// 128x128 block tile, BK=8, 256 threads, 8x8 microtile per thread.
// ---------------------------------------------------------------------------
__global__ __launch_bounds__(256) void sgemm_abt(
    const float* __restrict__ A, const float* __restrict__ Bm,
    float* __restrict__ Cm, int M, int N, int K)
{
    __shared__ __align__(16) float As[8][132];
    __shared__ __align__(16) float Bs[8][132];

    const int tid = threadIdx.x;
    const int tx = tid & 15;        // 0..15 -> N microtile
    const int ty = tid >> 4;        // 0..15 -> M microtile
    const int bm = blockIdx.y * 128;
    const int bn = blockIdx.x * 128;

    const int lrow = tid >> 1;              // 0..127
    const int lk   = (tid & 1) * 4;         // 0 or 4

    const float* Ap = A + (size_t)(bm + lrow) * K + lk;
    const float* Bp = Bm + (size_t)(bn + lrow) * K + lk;

    float acc[8][8];
#pragma unroll
    for (int i = 0; i < 8; i++)
#pragma unroll
        for (int j = 0; j < 8; j++) acc[i][j] = 0.0f;

    for (int k0 = 0; k0 < K; k0 += 8) {
        float4 av = *(const float4*)(Ap + k0);
        float4 bv = *(const float4*)(Bp + k0);
        __syncthreads();
        As[lk + 0][lrow] = av.x; As[lk + 1][lrow] = av.y;
        As[lk + 2][lrow] = av.z; As[lk + 3][lrow] = av.w;
        Bs[lk + 0][lrow] = bv.x; Bs[lk + 1][lrow] = bv.y;
        Bs[lk + 2][lrow] = bv.z; Bs[lk + 3][lrow] = bv.w;
        __syncthreads();
#pragma unroll
        for (int kk = 0; kk < 8; kk++) {
            float a[8], b[8];
            *(float4*)(a)     = *(const float4*)&As[kk][ty * 8];
            *(float4*)(a + 4) = *(const float4*)&As[kk][ty * 8 + 4];
            *(float4*)(b)     = *(const float4*)&Bs[kk][tx * 8];
            *(float4*)(b + 4) = *(const float4*)&Bs[kk][tx * 8 + 4];
#pragma unroll
            for (int i = 0; i < 8; i++)
#pragma unroll
                for (int j = 0; j < 8; j++)
                    acc[i][j] += a[i] * b[j];
        }
    }

#pragma unroll
    for (int i = 0; i < 8; i++) {
        float* cp = Cm + (size_t)(bm + ty * 8 + i) * N + bn + tx * 8;
        *(float4*)(cp)     = make_float4(acc[i][0], acc[i][1], acc[i][2], acc[i][3]);
        *(float4*)(cp + 4) = make_float4(acc[i][4], acc[i][5], acc[i][6], acc[i][7]);
    }
}

// ---------------------------------------------------------------------------
// RMSNorm(q,k) + RoPE + head-split into [B,H,T,D] layout.
// Block: (32,4) -> 4 heads per block, one warp per head; lane i owns pair (i, i+32).
// ---------------------------------------------------------------------------
__global__ void norm_rope_kernel(const float* __restrict__ qkv)
{
    const int lane = threadIdx.x;                 // 0..31
    const int h = blockIdx.y * 4 + threadIdx.y;   // 0..15
    const int bt = blockIdx.x;                    // 0..B*T-1
    const int b = bt / TT;
    const int t = bt % TT;

    const float* row = qkv + (size_t)bt * 3 * CC;
    float q0 = row[h * 64 + lane],           q1 = row[h * 64 + lane + 32];
    float k0 = row[CC + h * 64 + lane],      k1 = row[CC + h * 64 + lane + 32];
    float v0 = row[2 * CC + h * 64 + lane],  v1 = row[2 * CC + h * 64 + lane + 32];

    float qs = q0 * q0 + q1 * q1;
    float ks = k0 * k0 + k1 * k1;
#pragma unroll
    for (int w = 16; w >= 1; w >>= 1) {
        qs += __shfl_xor_sync(0xffffffffu, qs, w);
        ks += __shfl_xor_sync(0xffffffffu, ks, w);
    }
    const float eps = 1.1920929e-7f;   // float32 machine eps (matches jnp.finfo)
    float qr = rsqrtf(qs * (1.0f / 64.0f) + eps);
    float kr = rsqrtf(ks * (1.0f / 64.0f) + eps);
    q0 *= qr; q1 *= qr; k0 *= kr; k1 *= kr;

    // inv_freq[lane] = 10000^(-lane/32)
    float inv = powf(10000.0f, -(float)lane * (1.0f / 32.0f));
    float ang = (float)t * inv;
    float sn, cs;
    sincosf(ang, &sn, &cs);

    float qo0 = q0 * cs - q1 * sn;
    float qo1 = q1 * cs + q0 * sn;
    float ko0 = k0 * cs - k1 * sn;
    float ko1 = k1 * cs + k0 * sn;

    size_t o = (((size_t)b * HH + h) * TT + t) * DD;
    g_q[o + lane] = qo0; g_q[o + lane + 32] = qo1;
    g_k[o + lane] = ko0; g_k[o + lane + 32] = ko1;
    g_v[o + lane] = v0;  g_v[o + lane + 32] = v1;
}

// ---------------------------------------------------------------------------
// Causal flash attention, fp32 SIMT.
// One block = 64 q-rows of one (b,h). 256 threads, 4x4 microtiles.
// smem: Qs[d][m] (pad 68), KP[64][68] (K as [d][n], reused as P[j][m]), Vs[j][d].
// ---------------------------------------------------------------------------
#define FLASH_SMEM_FLOATS (64 * 68 * 2 + 64 * 64)
#define FLASH_SMEM_BYTES  (FLASH_SMEM_FLOATS * 4)

__global__ __launch_bounds__(256) void flash_kernel()
{
    extern __shared__ __align__(16) float smem[];
    float* Qs = smem;                 // [64][68]  Qs[d*68 + m]
    float* KP = smem + 64 * 68;       // [64][68]  K: KP[d*68+n]; later P: KP[j*68+m]
    float* Vs = KP + 64 * 68;         // [64][64]  Vs[j*64 + d]

    const int tid = threadIdx.x;
    const int tx = tid & 15;          // key / d-output microtile index
    const int ty = tid >> 4;          // q-row microtile index
    const int tx4 = tx * 4, ty4 = ty * 4;
    const int qt = blockIdx.x;
    const int bh = blockIdx.y;
    const int qbase = qt * 64;

    const float* Q = g_q + (size_t)bh * TT * DD;
    const float* K = g_k + (size_t)bh * TT * DD;
    const float* V = g_v + (size_t)bh * TT * DD;

    // Load Q tile (transposed to [d][m])
#pragma unroll
    for (int i = 0; i < 4; i++) {
        int idx = tid + i * 256;
        int r = idx >> 4;
        int dv = (idx & 15) * 4;
        float4 v4 = *(const float4*)(Q + (size_t)(qbase + r) * 64 + dv);
        Qs[(dv + 0) * 68 + r] = v4.x;
        Qs[(dv + 1) * 68 + r] = v4.y;
        Qs[(dv + 2) * 68 + r] = v4.z;
        Qs[(dv + 3) * 68 + r] = v4.w;
    }

    float o[4][4] = {};
    float mrow[4] = {-1e30f, -1e30f, -1e30f, -1e30f};
    float lrow[4] = {};

    for (int kt = 0; kt <= qt; kt++) {
        const int kbase = kt * 64;
        __syncthreads();   // previous P·V reads done before overwriting KP/Vs
#pragma unroll
        for (int i = 0; i < 4; i++) {
            int idx = tid + i * 256;
            int r = idx >> 4;
            int dv = (idx & 15) * 4;
            float4 kv = *(const float4*)(K + (size_t)(kbase + r) * 64 + dv);
            KP[(dv + 0) * 68 + r] = kv.x;
            KP[(dv + 1) * 68 + r] = kv.y;
            KP[(dv + 2) * 68 + r] = kv.z;
            KP[(dv + 3) * 68 + r] = kv.w;
            float4 vv = *(const float4*)(V + (size_t)(kbase + r) * 64 + dv);
            *(float4*)&Vs[r * 64 + dv] = vv;
        }
        __syncthreads();

        // S = Q K^T
        float s[4][4] = {};
#pragma unroll 8
        for (int d = 0; d < 64; d++) {
            float aa[4], bb[4];
            *(float4*)aa = *(const float4*)&Qs[d * 68 + ty4];
            *(float4*)bb = *(const float4*)&KP[d * 68 + tx4];
#pragma unroll
            for (int i = 0; i < 4; i++)
#pragma unroll
                for (int j = 0; j < 4; j++)
                    s[i][j] += aa[i] * bb[j];
        }

        const bool diag = (kt == qt);
#pragma unroll
        for (int i = 0; i < 4; i++)
#pragma unroll
            for (int j = 0; j < 4; j++) {
                s[i][j] *= 0.125f;                       // d_head^-0.5
                if (diag && (tx4 + j > ty4 + i)) s[i][j] = -1e30f;
            }

        // row max (16-lane groups share a q-row set)
        float tmax[4];
#pragma unroll
        for (int i = 0; i < 4; i++) {
            float mx = fmaxf(fmaxf(s[i][0], s[i][1]), fmaxf(s[i][2], s[i][3]));
#pragma unroll
            for (int w = 8; w >= 1; w >>= 1)
                mx = fmaxf(mx, __shfl_xor_sync(0xffffffffu, mx, w));
            tmax[i] = mx;
        }

        float alpha[4];
#pragma unroll
        for (int i = 0; i < 4; i++) {
            float mnew = fmaxf(mrow[i], tmax[i]);
            alpha[i] = __expf(mrow[i] - mnew);
            mrow[i] = mnew;
        }

        float rs[4];
#pragma unroll
        for (int i = 0; i < 4; i++) {
            float sum = 0.0f;
#pragma unroll
            for (int j = 0; j < 4; j++) {
                s[i][j] = __expf(s[i][j] - mrow[i]);
                sum += s[i][j];
            }
#pragma unroll
            for (int w = 8; w >= 1; w >>= 1)
                sum += __shfl_xor_sync(0xffffffffu, sum, w);
            rs[i] = sum;
        }

#pragma unroll
        for (int i = 0; i < 4; i++) {
            lrow[i] = lrow[i] * alpha[i] + rs[i];
#pragma unroll
            for (int j = 0; j < 4; j++) o[i][j] *= alpha[i];
        }

        __syncthreads();   // everyone done reading KP (K) before P overwrite
#pragma unroll
        for (int i = 0; i < 4; i++)
#pragma unroll
            for (int j = 0; j < 4; j++)
                KP[(tx4 + j) * 68 + ty4 + i] = s[i][j];
        __syncthreads();

        // O += P V
#pragma unroll 8
        for (int j = 0; j < 64; j++) {
            float aa[4], bb[4];
            *(float4*)aa = *(const float4*)&KP[j * 68 + ty4];
            *(float4*)bb = *(const float4*)&Vs[j * 64 + tx4];
#pragma unroll
            for (int i = 0; i < 4; i++)
#pragma unroll
                for (int dj = 0; dj < 4; dj++)
                    o[i][dj] += aa[i] * bb[dj];
        }
    }

    // Epilogue: normalize, write to [B,T,C] (reassemble heads)
    const int b = bh / HH;
    const int h = bh % HH;
#pragma unroll
    for (int i = 0; i < 4; i++) {
        float inv_l = 1.0f / lrow[i];
        float* yp = g_y + ((size_t)(b * TT + qbase + ty4 + i)) * CC + h * 64 + tx4;
        *(float4*)yp = make_float4(o[i][0] * inv_l, o[i][1] * inv_l,
                                   o[i][2] * inv_l, o[i][3] * inv_l);
    }
}

// ---------------------------------------------------------------------------
extern "C" void kernel_launch(void* const* d_in, const int* in_sizes, int n_in,
                              void* d_out, int out_size)
{
    const float* x      = (const float*)d_in[0];   // [B,T,C]
    const float* w_attn = (const float*)d_in[1];   // [3C,C]
    const float* w_proj = (const float*)d_in[2];   // [C,C]
    float* out = (float*)d_out;                    // [B,T,C]

    float *qkv, *y;
    cudaGetSymbolAddress((void**)&qkv, g_qkv);
    cudaGetSymbolAddress((void**)&y, g_y);

    // 1) QKV projection: [4096,3072] = x * w_attn^T
    sgemm_abt<<<dim3(3 * CC / 128, BB * TT / 128), 256>>>(x, w_attn, qkv,
                                                          BB * TT, 3 * CC, CC);
    // 2) RMSNorm + RoPE + split to [B,H,T,D]
    norm_rope_kernel<<<dim3(BB * TT, HH / 4), dim3(32, 4)>>>(qkv);

    // 3) Causal flash attention
    cudaFuncSetAttribute(flash_kernel, cudaFuncAttributeMaxDynamicSharedMemorySize,
                         FLASH_SMEM_BYTES);
    flash_kernel<<<dim3(TT / 64, BB * HH), 256, FLASH_SMEM_BYTES>>>();

    // 4) Output projection: [4096,1024] = y * w_proj^T
    sgemm_abt<<<dim3(CC / 128, BB * TT / 128), 256>>>(y, w_proj, out,
                                                      BB * TT, CC, CC);
}

// round 3
// speedup vs baseline: 2.5691x; 2.5691x over previous
#include <cuda_runtime.h>
#include <math.h>

// Problem constants
#define BB 2
#define TT 2048
#define HH 16
#define DD 64
#define CC 1024

// Scratch (device globals: allocation-free per harness rules)
__device__ float g_qkv[BB * TT * 3 * CC];
__device__ float g_q[BB * HH * TT * DD];
__device__ float g_k[BB * HH * TT * DD];
__device__ float g_v[BB * HH * TT * DD];
__device__ float g_y[BB * TT * CC];

// ---------------------------------------------------------------------------
// tf32 helpers
// ---------------------------------------------------------------------------
__device__ __forceinline__ unsigned tf32u(float x) {
    unsigned u;
    asm("cvt.rna.tf32.f32 %0, %1;" : "=r"(u) : "f"(x));
    return u;
}
__device__ __forceinline__ float tf32f(float x) {
    return __uint_as_float(tf32u(x));
}

// mma.sync m16n8k8 tf32, D += A*B (in-place accumulate)
__device__ __forceinline__ void mma_tf32(float* d,
    unsigned a0, unsigned a1, unsigned a2, unsigned a3,
    unsigned b0, unsigned b1)
{
    asm volatile(
        "mma.sync.aligned.m16n8k8.row.col.f32.tf32.tf32.f32 "
        "{%0,%1,%2,%3}, {%4,%5,%6,%7}, {%8,%9}, {%0,%1,%2,%3};\n"
        : "+f"(d[0]), "+f"(d[1]), "+f"(d[2]), "+f"(d[3])
        : "r"(a0), "r"(a1), "r"(a2), "r"(a3), "r"(b0), "r"(b1));
}

// ---------------------------------------------------------------------------
// tf32 tensor-core GEMM: C[m][n] = sum_k A[m][k] * B[n][k]  (C = A * B^T)
// 128x128 block tile, BK=32, 256 threads (8 warps), warp tile 64x32.
// ---------------------------------------------------------------------------
#define GP 36   // smem row pitch (floats): 36 mod 32 = 4 -> conflict-free frags

__global__ __launch_bounds__(256) void mma_gemm_abt(
    const float* __restrict__ A, const float* __restrict__ Bm,
    float* __restrict__ Cm, int M, int N, int K)
{
    __shared__ __align__(16) unsigned As[128 * GP];
    __shared__ __align__(16) unsigned Bs[128 * GP];

    const int tid  = threadIdx.x;
    const int warp = tid >> 5;
    const int lane = tid & 31;
    const int g = lane >> 2;     // groupID 0..7
    const int c = lane & 3;      // thread-in-group 0..3

    const int wm = (warp & 1) * 64;   // warp M offset
    const int wn = (warp >> 1) * 32;  // warp N offset

    const int bm = blockIdx.y * 128;
    const int bn = blockIdx.x * 128;

    const int lrow = tid >> 3;         // 0..31
    const int lcol = (tid & 7) * 4;    // 0,4,...,28

    float acc[4][4][4];
#pragma unroll
    for (int i = 0; i < 4; i++)
#pragma unroll
        for (int j = 0; j < 4; j++)
#pragma unroll
            for (int r = 0; r < 4; r++) acc[i][j][r] = 0.0f;

    for (int k0 = 0; k0 < K; k0 += 32) {
        float4 va[4], vb[4];
#pragma unroll
        for (int i = 0; i < 4; i++) {
            va[i] = *(const float4*)(A + (size_t)(bm + lrow + i * 32) * K + k0 + lcol);
            vb[i] = *(const float4*)(Bm + (size_t)(bn + lrow + i * 32) * K + k0 + lcol);
        }
        __syncthreads();
#pragma unroll
        for (int i = 0; i < 4; i++) {
            unsigned* ap = &As[(lrow + i * 32) * GP + lcol];
            ap[0] = tf32u(va[i].x); ap[1] = tf32u(va[i].y);
            ap[2] = tf32u(va[i].z); ap[3] = tf32u(va[i].w);
            unsigned* bp = &Bs[(lrow + i * 32) * GP + lcol];
            bp[0] = tf32u(vb[i].x); bp[1] = tf32u(vb[i].y);
            bp[2] = tf32u(vb[i].z); bp[3] = tf32u(vb[i].w);
        }
        __syncthreads();

#pragma unroll
        for (int ks = 0; ks < 4; ks++) {
            const int kk = ks * 8;
            unsigned af[4][4];
#pragma unroll
            for (int mt = 0; mt < 4; mt++) {
                const int r0 = wm + mt * 16 + g;
                af[mt][0] = As[r0 * GP + kk + c];
                af[mt][1] = As[(r0 + 8) * GP + kk + c];
                af[mt][2] = As[r0 * GP + kk + c + 4];
                af[mt][3] = As[(r0 + 8) * GP + kk + c + 4];
            }
            unsigned bf[4][2];
#pragma unroll
            for (int nt = 0; nt < 4; nt++) {
                const int n0 = wn + nt * 8 + g;
                bf[nt][0] = Bs[n0 * GP + kk + c];
                bf[nt][1] = Bs[n0 * GP + kk + c + 4];
            }
#pragma unroll
            for (int mt = 0; mt < 4; mt++)
#pragma unroll
                for (int nt = 0; nt < 4; nt++)
                    mma_tf32(acc[mt][nt], af[mt][0], af[mt][1], af[mt][2], af[mt][3],
                             bf[nt][0], bf[nt][1]);
        }
        __syncthreads();
    }

#pragma unroll
    for (int mt = 0; mt < 4; mt++) {
        const int r0 = bm + wm + mt * 16 + g;
#pragma unroll
        for (int nt = 0; nt < 4; nt++) {
            const int c0 = bn + wn + nt * 8 + 2 * c;
            *(float2*)(Cm + (size_t)r0 * N + c0) = make_float2(acc[mt][nt][0], acc[mt][nt][1]);
            *(float2*)(Cm + (size_t)(r0 + 8) * N + c0) = make_float2(acc[mt][nt][2], acc[mt][nt][3]);
        }
    }
}

// ---------------------------------------------------------------------------
// RMSNorm(q,k) + RoPE + head-split into [B,H,T,D]; outputs tf32-rounded.
// ---------------------------------------------------------------------------
__global__ void norm_rope_kernel(const float* __restrict__ qkv)
{
    const int lane = threadIdx.x;
    const int h = blockIdx.y * 4 + threadIdx.y;
    const int bt = blockIdx.x;
    const int b = bt / TT;
    const int t = bt % TT;

    const float* row = qkv + (size_t)bt * 3 * CC;
    float q0 = row[h * 64 + lane],           q1 = row[h * 64 + lane + 32];
    float k0 = row[CC + h * 64 + lane],      k1 = row[CC + h * 64 + lane + 32];
    float v0 = row[2 * CC + h * 64 + lane],  v1 = row[2 * CC + h * 64 + lane + 32];

    float qs = q0 * q0 + q1 * q1;
    float ks = k0 * k0 + k1 * k1;
#pragma unroll
    for (int w = 16; w >= 1; w >>= 1) {
        qs += __shfl_xor_sync(0xffffffffu, qs, w);
        ks += __shfl_xor_sync(0xffffffffu, ks, w);
    }
    const float eps = 1.1920929e-7f;
    float qr = rsqrtf(qs * (1.0f / 64.0f) + eps);
    float kr = rsqrtf(ks * (1.0f / 64.0f) + eps);
    q0 *= qr; q1 *= qr; k0 *= kr; k1 *= kr;

    float inv = powf(10000.0f, -(float)lane * (1.0f / 32.0f));
    float ang = (float)t * inv;
    float sn, cs;
    sincosf(ang, &sn, &cs);

    float qo0 = q0 * cs - q1 * sn;
    float qo1 = q1 * cs + q0 * sn;
    float ko0 = k0 * cs - k1 * sn;
    float ko1 = k1 * cs + k0 * sn;

    size_t o = (((size_t)b * HH + h) * TT + t) * DD;
    g_q[o + lane] = tf32f(qo0); g_q[o + lane + 32] = tf32f(qo1);
    g_k[o + lane] = tf32f(ko0); g_k[o + lane + 32] = tf32f(ko1);
    g_v[o + lane] = tf32f(v0);  g_v[o + lane + 32] = tf32f(v1);
}

// ---------------------------------------------------------------------------
// Causal flash attention with tf32 mma.
// Block: 128 threads (4 warps), 64 q-rows; warp w owns q rows [16w, 16w+16).
// smem: Qs/Ps [64][68] (Q staging, then P), Kt [d][key] [64][68], Vs [key][d].
// ---------------------------------------------------------------------------
#define FD 68
#define FLASH_SMEM_BYTES (3 * 64 * FD * 4)

__global__ __launch_bounds__(128) void flash_mma()
{
    extern __shared__ __align__(16) float smem[];
    float* Ps = smem;                  // Q staging, then P  [64][FD]
    float* Kt = smem + 64 * FD;        // K^T [d][key]       [64][FD]
    float* Vs = smem + 2 * 64 * FD;    // V   [key][d]       [64][FD]

    const int tid  = threadIdx.x;
    const int warp = tid >> 5;
    const int lane = tid & 31;
    const int g = lane >> 2;
    const int c = lane & 3;
    const int qr = warp * 16;          // warp's q-row offset inside tile

    const int qt = blockIdx.x;
    const int bh = blockIdx.y;
    const int qbase = qt * 64;

    const float* Q = g_q + (size_t)bh * TT * DD;
    const float* K = g_k + (size_t)bh * TT * DD;
    const float* V = g_v + (size_t)bh * TT * DD;

    // Stage Q tile to smem (coalesced), then pull A-fragments into registers.
#pragma unroll
    for (int i = 0; i < 8; i++) {
        int idx = tid + i * 128;          // 0..1023 float4s
        int r = idx >> 4;
        int dv = (idx & 15) * 4;
        float4 v4 = *(const float4*)(Q + (size_t)(qbase + r) * 64 + dv);
        *(float4*)&Ps[r * FD + dv] = v4;
    }
    __syncthreads();

    unsigned qf[8][4];   // Q as A-fragments over 8 k(d)-steps (already tf32)
#pragma unroll
    for (int ks = 0; ks < 8; ks++) {
        const int kk = ks * 8;
        qf[ks][0] = __float_as_uint(Ps[(qr + g) * FD + kk + c]);
        qf[ks][1] = __float_as_uint(Ps[(qr + g + 8) * FD + kk + c]);
        qf[ks][2] = __float_as_uint(Ps[(qr + g) * FD + kk + c + 4]);
        qf[ks][3] = __float_as_uint(Ps[(qr + g + 8) * FD + kk + c + 4]);
    }

    float oacc[8][4];
#pragma unroll
    for (int nt = 0; nt < 8; nt++)
#pragma unroll
        for (int r = 0; r < 4; r++) oacc[nt][r] = 0.0f;
    float m0 = -1e30f, m1 = -1e30f, l0 = 0.0f, l1 = 0.0f;

    for (int kt = 0; kt <= qt; kt++) {
        const int kbase = kt * 64;
        __syncthreads();   // prior PV reads of Vs done; Q frag reads done
#pragma unroll
        for (int i = 0; i < 8; i++) {
            int idx = tid + i * 128;
            int r = idx >> 4;
            int dv = (idx & 15) * 4;
            float4 kv = *(const float4*)(K + (size_t)(kbase + r) * 64 + dv);
            Kt[(dv + 0) * FD + r] = kv.x;
            Kt[(dv + 1) * FD + r] = kv.y;
            Kt[(dv + 2) * FD + r] = kv.z;
            Kt[(dv + 3) * FD + r] = kv.w;
            float4 vv = *(const float4*)(V + (size_t)(kbase + r) * 64 + dv);
            *(float4*)&Vs[r * FD + dv] = vv;
        }
        __syncthreads();

        // S = Q K^T  (8 n-tiles of 8 keys)
        float sacc[8][4];
#pragma unroll
        for (int nt = 0; nt < 8; nt++)
#pragma unroll
            for (int r = 0; r < 4; r++) sacc[nt][r] = 0.0f;

#pragma unroll
        for (int ks = 0; ks < 8; ks++) {
            const int kk = ks * 8;
#pragma unroll
            for (int nt = 0; nt < 8; nt++) {
                unsigned b0 = __float_as_uint(Kt[(kk + c) * FD + nt * 8 + g]);
                unsigned b1 = __float_as_uint(Kt[(kk + c + 4) * FD + nt * 8 + g]);
                mma_tf32(sacc[nt], qf[ks][0], qf[ks][1], qf[ks][2], qf[ks][3], b0, b1);
            }
        }

        // scale + causal mask
        const bool diag = (kt == qt);
#pragma unroll
        for (int nt = 0; nt < 8; nt++) {
            const int key0 = nt * 8 + 2 * c;   // local key of regs 0/2
#pragma unroll
            for (int r = 0; r < 4; r++) sacc[nt][r] *= 0.125f;
            if (diag) {
                const int q0i = qr + g, q1i = qr + g + 8;
                if (key0 > q0i)     sacc[nt][0] = -1e30f;
                if (key0 + 1 > q0i) sacc[nt][1] = -1e30f;
                if (key0 > q1i)     sacc[nt][2] = -1e30f;
                if (key0 + 1 > q1i) sacc[nt][3] = -1e30f;
            }
        }

        // row max (rows g and g+8) across quad lanes
        float t0 = -1e30f, t1 = -1e30f;
#pragma unroll
        for (int nt = 0; nt < 8; nt++) {
            t0 = fmaxf(t0, fmaxf(sacc[nt][0], sacc[nt][1]));
            t1 = fmaxf(t1, fmaxf(sacc[nt][2], sacc[nt][3]));
        }
#pragma unroll
        for (int w = 1; w <= 2; w <<= 1) {
            t0 = fmaxf(t0, __shfl_xor_sync(0xffffffffu, t0, w));
            t1 = fmaxf(t1, __shfl_xor_sync(0xffffffffu, t1, w));
        }
        float mn0 = fmaxf(m0, t0), mn1 = fmaxf(m1, t1);
        float al0 = __expf(m0 - mn0), al1 = __expf(m1 - mn1);
        m0 = mn0; m1 = mn1;

        // exponentiate, row sums, write P (tf32) to Ps
        float rs0 = 0.0f, rs1 = 0.0f;
        __syncwarp();   // prior PV reads of Ps done (same warp rows)
#pragma unroll
        for (int nt = 0; nt < 8; nt++) {
            float p0 = __expf(sacc[nt][0] - m0);
            float p1 = __expf(sacc[nt][1] - m0);
            float p2 = __expf(sacc[nt][2] - m1);
            float p3 = __expf(sacc[nt][3] - m1);
            rs0 += p0 + p1; rs1 += p2 + p3;
            const int col = nt * 8 + 2 * c;
            *(float2*)&Ps[(qr + g) * FD + col]     = make_float2(tf32f(p0), tf32f(p1));
            *(float2*)&Ps[(qr + g + 8) * FD + col] = make_float2(tf32f(p2), tf32f(p3));
        }
#pragma unroll
        for (int w = 1; w <= 2; w <<= 1) {
            rs0 += __shfl_xor_sync(0xffffffffu, rs0, w);
            rs1 += __shfl_xor_sync(0xffffffffu, rs1, w);
        }
        l0 = l0 * al0 + rs0;
        l1 = l1 * al1 + rs1;
#pragma unroll
        for (int nt = 0; nt < 8; nt++) {
            oacc[nt][0] *= al0; oacc[nt][1] *= al0;
            oacc[nt][2] *= al1; oacc[nt][3] *= al1;
        }
        __syncwarp();   // P visible to whole warp

        // O += P V   (contraction over 64 keys, 8 n-tiles over d)
#pragma unroll
        for (int ks = 0; ks < 8; ks++) {
            const int kk = ks * 8;
            unsigned pf0 = __float_as_uint(Ps[(qr + g) * FD + kk + c]);
            unsigned pf1 = __float_as_uint(Ps[(qr + g + 8) * FD + kk + c]);
            unsigned pf2 = __float_as_uint(Ps[(qr + g) * FD + kk + c + 4]);
            unsigned pf3 = __float_as_uint(Ps[(qr + g + 8) * FD + kk + c + 4]);
#pragma unroll
            for (int nt = 0; nt < 8; nt++) {
                unsigned b0 = __float_as_uint(Vs[(kk + c) * FD + nt * 8 + g]);
                unsigned b1 = __float_as_uint(Vs[(kk + c + 4) * FD + nt * 8 + g]);
                mma_tf32(oacc[nt], pf0, pf1, pf2, pf3, b0, b1);
            }
        }
    }

    // Epilogue: normalize, write to [B,T,C]
    const int b = bh / HH;
    const int h = bh % HH;
    const float inv0 = 1.0f / l0, inv1 = 1.0f / l1;
    const int row0 = qbase + qr + g;
#pragma unroll
    for (int nt = 0; nt < 8; nt++) {
        const int col = h * 64 + nt * 8 + 2 * c;
        *(float2*)(g_y + (size_t)(b * TT + row0) * CC + col) =
            make_float2(oacc[nt][0] * inv0, oacc[nt][1] * inv0);
        *(float2*)(g_y + (size_t)(b * TT + row0 + 8) * CC + col) =
            make_float2(oacc[nt][2] * inv1, oacc[nt][3] * inv1);
    }
}

// ---------------------------------------------------------------------------
extern "C" void kernel_launch(void* const* d_in, const int* in_sizes, int n_in,
                              void* d_out, int out_size)
{
    const float* x      = (const float*)d_in[0];
    const float* w_attn = (const float*)d_in[1];
    const float* w_proj = (const float*)d_in[2];
    float* out = (float*)d_out;

    float *qkv, *y;
    cudaGetSymbolAddress((void**)&qkv, g_qkv);
    cudaGetSymbolAddress((void**)&y, g_y);

    // 1) QKV projection: [4096,3072] = x * w_attn^T
    mma_gemm_abt<<<dim3(3 * CC / 128, BB * TT / 128), 256>>>(x, w_attn, qkv,
                                                             BB * TT, 3 * CC, CC);
    // 2) RMSNorm + RoPE + head split (tf32-rounded outputs)
    norm_rope_kernel<<<dim3(BB * TT, HH / 4), dim3(32, 4)>>>(qkv);

    // 3) Causal flash attention (tf32 tensor cores)
    cudaFuncSetAttribute(flash_mma, cudaFuncAttributeMaxDynamicSharedMemorySize,
                         FLASH_SMEM_BYTES);
    flash_mma<<<dim3(TT / 64, BB * HH), 128, FLASH_SMEM_BYTES>>>();

    // 4) Output projection: [4096,1024] = y * w_proj^T
    mma_gemm_abt<<<dim3(CC / 128, BB * TT / 128), 256>>>(y, w_proj, out,
                                                         BB * TT, CC, CC);
}